// round 1
// baseline (speedup 1.0000x reference)
#include <cuda_runtime.h>
#include <math.h>

// Problem constants
#define Bn   4
#define Tn   256
#define Vn   1024
#define Sn   64
#define DIMn 1024
#define CVn  256
#define BT   (Bn*Tn)          // 1024

// ---------------- scratch (__device__ globals; no allocations) ----------------
__device__ float g_Wuk[CVn*DIMn];   // Wu@Wk  [256,1024]
__device__ float g_Wuv[CVn*DIMn];   // Wu@Wv  [256,1024]
__device__ float g_buk[DIMn];
__device__ float g_buv[DIMn];
__device__ int   g_idx[BT*Sn];
__device__ float g_bq[BT];          // buk . q
__device__ float g_P[BT*CVn];       // Wuk @ q  per (b,t)
__device__ float g_logit[BT*Sn];
__device__ float g_sm[BT*Sn];
__device__ float g_w[BT*CVn];       // sum_s sm * vg
__device__ float g_alpha[BT];       // sum_s sm
__device__ int   g_mask_u8;

// ---------------- mask dtype detection ----------------
// bool mask -> 1-byte elements, ~6.25% ones everywhere.
// int32/float32 mask -> bytes at (pos % 4 == 1) are always 0.
__global__ void detect_mask_kernel(const unsigned char* __restrict__ m) {
    __shared__ int red[256];
    int tid = threadIdx.x;
    int cnt = 0;
    for (int i = tid*4 + 1; i < Bn*Vn*Tn; i += 1024) cnt += (m[i] != 0);
    red[tid] = cnt; __syncthreads();
    for (int off = 128; off > 0; off >>= 1) {
        if (tid < off) red[tid] += red[tid+off];
        __syncthreads();
    }
    if (tid == 0) g_mask_u8 = (red[0] > 0) ? 1 : 0;
}

// ---------------- generic 64x64 tile fp32 GEMM ----------------
// C[M,N] = A[M,K] * B   ; B row-major [K,N] (TRANSB=0) or [N,K] (TRANSB=1)
// EPI: C[m,n] = acc + ep_alpha[m]*ep_bias[n] + ep_add[m*N+n]
template<int M, int N, int K, bool TRANSB, bool EPI>
__device__ __forceinline__ void gemm_dev(const float* __restrict__ A,
                                         const float* __restrict__ Bm,
                                         float* __restrict__ C,
                                         const float* __restrict__ ep_alpha,
                                         const float* __restrict__ ep_bias,
                                         const float* __restrict__ ep_add)
{
    __shared__ __align__(16) float As[16][64];
    __shared__ __align__(16) float Bs[16][64];
    const int tid = threadIdx.x;
    const int tx = tid & 15, ty = tid >> 4;
    const int m0 = blockIdx.y * 64, n0 = blockIdx.x * 64;

    float acc[4][4];
    #pragma unroll
    for (int i = 0; i < 4; i++)
        #pragma unroll
        for (int j = 0; j < 4; j++) acc[i][j] = 0.f;

    for (int kt = 0; kt < K; kt += 16) {
        {   // A tile: 64 rows x 16 k, stored transposed As[k][m]
            int r = tid >> 2; int c = (tid & 3) << 2;
            float4 v = *(const float4*)(A + (size_t)(m0 + r)*K + kt + c);
            As[c+0][r] = v.x; As[c+1][r] = v.y; As[c+2][r] = v.z; As[c+3][r] = v.w;
        }
        if (!TRANSB) {
            int r = tid >> 4; int c = (tid & 15) << 2;
            *(float4*)&Bs[r][c] = *(const float4*)(Bm + (size_t)(kt + r)*N + n0 + c);
        } else {
            int r = tid >> 2; int c = (tid & 3) << 2;
            float4 v = *(const float4*)(Bm + (size_t)(n0 + r)*K + kt + c);
            Bs[c+0][r] = v.x; Bs[c+1][r] = v.y; Bs[c+2][r] = v.z; Bs[c+3][r] = v.w;
        }
        __syncthreads();
        #pragma unroll
        for (int kk = 0; kk < 16; kk++) {
            float4 ar = *(const float4*)&As[kk][ty << 2];
            float4 br = *(const float4*)&Bs[kk][tx << 2];
            float a[4] = {ar.x, ar.y, ar.z, ar.w};
            float b[4] = {br.x, br.y, br.z, br.w};
            #pragma unroll
            for (int i = 0; i < 4; i++)
                #pragma unroll
                for (int j = 0; j < 4; j++) acc[i][j] += a[i]*b[j];
        }
        __syncthreads();
    }

    #pragma unroll
    for (int i = 0; i < 4; i++) {
        int m = m0 + (ty << 2) + i;
        #pragma unroll
        for (int j = 0; j < 4; j++) {
            int n = n0 + (tx << 2) + j;
            float val = acc[i][j];
            if (EPI) val += ep_alpha[m]*ep_bias[n] + ep_add[(size_t)m*N + n];
            C[(size_t)m*N + n] = val;
        }
    }
}

__global__ void __launch_bounds__(256)
k1_kernel(const float* __restrict__ Wu, const float* __restrict__ Wk,
          const float* __restrict__ Wv) {
    gemm_dev<CVn, DIMn, DIMn, false, false>(Wu, blockIdx.z ? Wv : Wk,
                                            blockIdx.z ? g_Wuv : g_Wuk,
                                            nullptr, nullptr, nullptr);
}

__global__ void __launch_bounds__(256)
k2b_kernel(const float* __restrict__ x) {
    // P[bt, i] = sum_d x[bt,d] * Wuk[i,d]   (B transposed layout)
    gemm_dev<BT, CVn, DIMn, true, false>(x, g_Wuk, g_P, nullptr, nullptr, nullptr);
}

__global__ void __launch_bounds__(256)
k6_kernel(const float* __restrict__ x, float* __restrict__ out) {
    // out[bt, j] = sum_i w[bt,i]*Wuv[i,j] + alpha[bt]*buv[j] + x[bt,j]
    gemm_dev<BT, DIMn, CVn, false, true>(g_w, g_Wuv, out, g_alpha, g_buv, x);
}

// ---------------- buk / buv ----------------
__global__ void bias_kernel(const float* __restrict__ bu,
                            const float* __restrict__ Wk,
                            const float* __restrict__ Wv) {
    __shared__ float sbu[DIMn];
    int tid = threadIdx.x;
    for (int i = tid; i < DIMn; i += 256) sbu[i] = bu[i];
    __syncthreads();
    const float* W = blockIdx.y ? Wv : Wk;
    float* outb = blockIdx.y ? g_buv : g_buk;
    int j = blockIdx.x*256 + tid;
    float acc = 0.f;
    for (int d = 0; d < DIMn; d++) acc += sbu[d]*W[(size_t)d*DIMn + j];
    outb[j] = acc;
}

// ---------------- index build (ordered selection) + bq ----------------
__global__ void build_idx_kernel(const void* __restrict__ maskp,
                                 const float* __restrict__ x) {
    int bt = blockIdx.x; int b = bt >> 8; int t = bt & 255;
    int tid = threadIdx.x;
    __shared__ int sc[256];
    __shared__ float sf[256];

    const bool u8 = (g_mask_u8 != 0);
    const unsigned char* m8 = (const unsigned char*)maskp;
    const int* m32 = (const int*)maskp;

    int vbase = tid << 2;
    int flags = 0, cnt = 0;
    #pragma unroll
    for (int u = 0; u < 4; u++) {
        int e = (b*Vn + vbase + u)*Tn + t;
        int mm = u8 ? (int)m8[e] : (m32[e] != 0);
        if (mm) { flags |= (1 << u); cnt++; }
    }
    sc[tid] = cnt; __syncthreads();
    for (int off = 1; off < 256; off <<= 1) {
        int v = (tid >= off) ? sc[tid - off] : 0;
        __syncthreads();
        sc[tid] += v;
        __syncthreads();
    }
    int pos = sc[tid] - cnt;
    int total = sc[255];
    #pragma unroll
    for (int u = 0; u < 4; u++)
        if (flags & (1 << u)) { if (pos < Sn) g_idx[bt*Sn + pos] = vbase + u; pos++; }
    if (tid == 0)
        for (int p = total; p < Sn; p++) g_idx[bt*Sn + p] = Vn;   // pad sentinel

    // bq = buk . q
    float a = 0.f;
    #pragma unroll
    for (int u = 0; u < 4; u++)
        a += x[(size_t)bt*DIMn + vbase + u] * g_buk[vbase + u];
    sf[tid] = a; __syncthreads();
    for (int off = 128; off > 0; off >>= 1) {
        if (tid < off) sf[tid] += sf[tid+off];
        __syncthreads();
    }
    if (tid == 0) g_bq[bt] = sf[0];
}

// ---------------- logits: qk[b,t,s] = (vg_s . P + bq)/32 + mask ----------------
__global__ void logits_kernel(const float* __restrict__ vision) {
    int bt = blockIdx.x; int b = bt >> 8; int tid = threadIdx.x;
    __shared__ float p_sh[CVn];
    __shared__ int idx_sh[Sn];
    p_sh[tid] = g_P[bt*CVn + tid];
    if (tid < Sn) idx_sh[tid] = g_idx[bt*Sn + tid];
    __syncthreads();
    int s = tid >> 2, lane = tid & 3;
    int idx = idx_sh[s];
    float acc = 0.f;
    if (idx < Vn) {
        const float* vrow = vision + (size_t)(b*Vn + idx)*CVn;
        #pragma unroll 8
        for (int c = lane; c < CVn; c += 4) acc += vrow[c]*p_sh[c];
    }
    acc += __shfl_down_sync(0xffffffffu, acc, 2, 4);
    acc += __shfl_down_sync(0xffffffffu, acc, 1, 4);
    if (lane == 0) {
        float lg = (acc + g_bq[bt]) * 0.03125f + (idx < Vn ? -100.0f : 0.0f);
        g_logit[bt*Sn + s] = lg;
    }
}

// ---------------- batch-global softmax over T*S = 16384 ----------------
__global__ void softmax_kernel() {
    int b = blockIdx.x; int tid = threadIdx.x;
    const int n = Tn*Sn;
    __shared__ float red[256];
    float* L = g_logit + b*n;
    float* Sm = g_sm + b*n;

    float mx = -1e30f;
    for (int i = tid; i < n; i += 256) mx = fmaxf(mx, L[i]);
    red[tid] = mx; __syncthreads();
    for (int off = 128; off > 0; off >>= 1) {
        if (tid < off) red[tid] = fmaxf(red[tid], red[tid+off]);
        __syncthreads();
    }
    mx = red[0]; __syncthreads();

    float sum = 0.f;
    for (int i = tid; i < n; i += 256) {
        float e = expf(L[i] - mx);
        Sm[i] = e; sum += e;
    }
    red[tid] = sum; __syncthreads();
    for (int off = 128; off > 0; off >>= 1) {
        if (tid < off) red[tid] += red[tid+off];
        __syncthreads();
    }
    float inv = 1.0f / red[0];
    for (int i = tid; i < n; i += 256) Sm[i] *= inv;
}

// ---------------- w[bt,c] = sum_s sm * vg[s,c] ; alpha[bt] = sum_s sm ----------------
__global__ void wsum_kernel(const float* __restrict__ vision) {
    int bt = blockIdx.x; int b = bt >> 8; int tid = threadIdx.x;
    __shared__ float sm_sh[Sn];
    __shared__ int idx_sh[Sn];
    if (tid < Sn) { sm_sh[tid] = g_sm[bt*Sn + tid]; idx_sh[tid] = g_idx[bt*Sn + tid]; }
    __syncthreads();
    float acc = 0.f;
    const float* vb = vision + (size_t)b*Vn*CVn;
    #pragma unroll 4
    for (int s = 0; s < Sn; s++) {
        int idx = idx_sh[s];
        if (idx < Vn) acc += sm_sh[s] * vb[(size_t)idx*CVn + tid];
    }
    g_w[bt*CVn + tid] = acc;
    if (tid < 32) {
        float a = sm_sh[tid] + sm_sh[tid + 32];
        for (int off = 16; off > 0; off >>= 1)
            a += __shfl_down_sync(0xffffffffu, a, off);
        if (tid == 0) g_alpha[bt] = a;
    }
}

// ---------------- launch ----------------
extern "C" void kernel_launch(void* const* d_in, const int* in_sizes, int n_in,
                              void* d_out, int out_size) {
    const float* x      = (const float*)d_in[0];
    const float* vision = (const float*)d_in[1];
    const void*  mask   = d_in[2];
    const float* Wu     = (const float*)d_in[3];
    const float* bu     = (const float*)d_in[4];
    const float* Wk     = (const float*)d_in[5];
    const float* Wv     = (const float*)d_in[6];
    float* out = (float*)d_out;

    detect_mask_kernel<<<1, 256>>>((const unsigned char*)mask);
    k1_kernel<<<dim3(DIMn/64, CVn/64, 2), 256>>>(Wu, Wk, Wv);   // Wuk, Wuv
    bias_kernel<<<dim3(DIMn/256, 2), 256>>>(bu, Wk, Wv);        // buk, buv
    build_idx_kernel<<<BT, 256>>>(mask, x);                     // idx, bq
    k2b_kernel<<<dim3(CVn/64, BT/64), 256>>>(x);                // P
    logits_kernel<<<BT, 256>>>(vision);                         // qk logits
    softmax_kernel<<<Bn, 256>>>();                              // batch-global softmax
    wsum_kernel<<<BT, 256>>>(vision);                           // w, alpha
    k6_kernel<<<dim3(DIMn/64, BT/64), 256>>>(x, out);           // final GEMM + residual
}

// round 2
// speedup vs baseline: 2.5922x; 2.5922x over previous
#include <cuda_runtime.h>
#include <math.h>
#include <stdint.h>

#define Bn   4
#define Tn   256
#define Vn   1024
#define Sn   64
#define DIMn 1024
#define CVn  256
#define BT   (Bn*Tn)          // 1024

// ---------------- scratch ----------------
__device__ float g_Wuk[CVn*DIMn];
__device__ float g_Wuv[CVn*DIMn];
__device__ float g_bias_part[2][8][DIMn];
__device__ float g_buk[DIMn];
__device__ float g_buv[DIMn];
__device__ int   g_idx[BT*Sn];
__device__ float g_bq[BT];
__device__ float g_P[BT*CVn];
__device__ float g_logit[BT*Sn];
__device__ float g_sm[BT*Sn];
__device__ float g_w[BT*CVn];
__device__ float g_alpha[BT];
__device__ int   g_mask_u8;

// ---------------- mask dtype detection (sampled: first 16KB) ----------------
__global__ void detect_mask_kernel(const unsigned char* __restrict__ m) {
    int tid = threadIdx.x;
    int cnt = 0;
    #pragma unroll
    for (int i = 0; i < 16; i++) {
        int pos = (tid * 16 + i) * 4 + 1;   // bytes at pos%4==1 within first 16KB
        cnt += (m[pos] != 0);
    }
    __shared__ int red[256];
    red[tid] = cnt; __syncthreads();
    for (int off = 128; off > 0; off >>= 1) {
        if (tid < off) red[tid] += red[tid + off];
        __syncthreads();
    }
    if (tid == 0) g_mask_u8 = (red[0] > 0) ? 1 : 0;
}

// ---------------- tf32 tensor-core GEMM ----------------
// C[M,N] = A[M,K](row) * B ; B row-major [K,N] (TRANSB=0) or [N,K] (TRANSB=1)
// block tile 128x64, 256 threads (8 warps, 4x2 of 32x32 warp tiles), k-step 16,
// double-buffered smem, k-major layout with pad 4 -> conflict-free fragment LDS.
#define KTILE 16

__device__ __forceinline__ float to_tf32(float x) {
    float r; asm("cvt.rna.tf32.f32 %0, %1;" : "=f"(r) : "f"(x)); return r;
}
__device__ __forceinline__ void mma_tf32(float c[4], const uint32_t a[4], const uint32_t b[2]) {
    asm volatile("mma.sync.aligned.m16n8k8.row.col.f32.tf32.tf32.f32 "
        "{%0,%1,%2,%3}, {%4,%5,%6,%7}, {%8,%9}, {%0,%1,%2,%3};"
        : "+f"(c[0]), "+f"(c[1]), "+f"(c[2]), "+f"(c[3])
        : "r"(a[0]), "r"(a[1]), "r"(a[2]), "r"(a[3]), "r"(b[0]), "r"(b[1]));
}

template<int N, int K, bool TRANSB, bool EPI>
__device__ __forceinline__ void gemm_tc(const float* __restrict__ A,
                                        const float* __restrict__ Bm,
                                        float* __restrict__ C,
                                        const float* __restrict__ ep_alpha,
                                        const float* __restrict__ ep_bias,
                                        const float* __restrict__ ep_add)
{
    __shared__ __align__(16) float As[2][KTILE][132];   // [k][m], pad 4
    __shared__ __align__(16) float Bs[2][KTILE][68];    // [k][n], pad 4

    const int tid  = threadIdx.x;
    const int lane = tid & 31, wid = tid >> 5;
    const int wm = (wid & 3) * 32;
    const int wn = (wid >> 2) * 32;
    const int m0 = blockIdx.y * 128;
    const int n0 = blockIdx.x * 64;

    // staging index precompute
    const int am0 = tid >> 2;            // A: idx = tid   -> m = idx>>2, kg = idx&3
    const int akg0 = tid & 3;
    const int am1 = (tid + 256) >> 2;
    const int akg1 = (tid + 256) & 3;
    const int bk  = tid >> 4;            // B no-trans: k row, 16 float4 per row
    const int bng = tid & 15;
    const int btn = tid >> 2;            // B trans: n row
    const int btkg = tid & 3;

    float acc[2][4][4];
    #pragma unroll
    for (int i = 0; i < 2; i++)
        #pragma unroll
        for (int j = 0; j < 4; j++)
            #pragma unroll
            for (int q = 0; q < 4; q++) acc[i][j][q] = 0.f;

    float4 ra0, ra1, rb;
    // prologue load tile 0
    ra0 = *(const float4*)(A + (size_t)(m0 + am0)*K + akg0*4);
    ra1 = *(const float4*)(A + (size_t)(m0 + am1)*K + akg1*4);
    if (!TRANSB) rb = *(const float4*)(Bm + (size_t)bk*N + n0 + bng*4);
    else         rb = *(const float4*)(Bm + (size_t)(n0 + btn)*K + btkg*4);

    const int niter = K / KTILE;
    // store tile 0
    {
        As[0][akg0*4+0][am0] = to_tf32(ra0.x); As[0][akg0*4+1][am0] = to_tf32(ra0.y);
        As[0][akg0*4+2][am0] = to_tf32(ra0.z); As[0][akg0*4+3][am0] = to_tf32(ra0.w);
        As[0][akg1*4+0][am1] = to_tf32(ra1.x); As[0][akg1*4+1][am1] = to_tf32(ra1.y);
        As[0][akg1*4+2][am1] = to_tf32(ra1.z); As[0][akg1*4+3][am1] = to_tf32(ra1.w);
        if (!TRANSB) {
            float4 t; t.x = to_tf32(rb.x); t.y = to_tf32(rb.y); t.z = to_tf32(rb.z); t.w = to_tf32(rb.w);
            *(float4*)&Bs[0][bk][bng*4] = t;
        } else {
            Bs[0][btkg*4+0][btn] = to_tf32(rb.x); Bs[0][btkg*4+1][btn] = to_tf32(rb.y);
            Bs[0][btkg*4+2][btn] = to_tf32(rb.z); Bs[0][btkg*4+3][btn] = to_tf32(rb.w);
        }
    }
    __syncthreads();

    for (int it = 0; it < niter; it++) {
        const int buf = it & 1;
        const bool hasnext = (it + 1 < niter);
        if (hasnext) {
            const int kt = (it + 1) * KTILE;
            ra0 = *(const float4*)(A + (size_t)(m0 + am0)*K + kt + akg0*4);
            ra1 = *(const float4*)(A + (size_t)(m0 + am1)*K + kt + akg1*4);
            if (!TRANSB) rb = *(const float4*)(Bm + (size_t)(kt + bk)*N + n0 + bng*4);
            else         rb = *(const float4*)(Bm + (size_t)(n0 + btn)*K + kt + btkg*4);
        }
        #pragma unroll
        for (int ks = 0; ks < KTILE; ks += 8) {
            uint32_t af[2][4], bf[4][2];
            #pragma unroll
            for (int mi = 0; mi < 2; mi++) {
                const int row = wm + mi*16 + (lane >> 2);
                const int col = ks + (lane & 3);
                af[mi][0] = __float_as_uint(As[buf][col  ][row  ]);
                af[mi][1] = __float_as_uint(As[buf][col  ][row+8]);
                af[mi][2] = __float_as_uint(As[buf][col+4][row  ]);
                af[mi][3] = __float_as_uint(As[buf][col+4][row+8]);
            }
            #pragma unroll
            for (int ni = 0; ni < 4; ni++) {
                const int bc = wn + ni*8 + (lane >> 2);
                bf[ni][0] = __float_as_uint(Bs[buf][ks   + (lane & 3)][bc]);
                bf[ni][1] = __float_as_uint(Bs[buf][ks+4 + (lane & 3)][bc]);
            }
            #pragma unroll
            for (int mi = 0; mi < 2; mi++)
                #pragma unroll
                for (int ni = 0; ni < 4; ni++)
                    mma_tf32(acc[mi][ni], af[mi], bf[ni]);
        }
        if (hasnext) {
            const int nb = buf ^ 1;
            As[nb][akg0*4+0][am0] = to_tf32(ra0.x); As[nb][akg0*4+1][am0] = to_tf32(ra0.y);
            As[nb][akg0*4+2][am0] = to_tf32(ra0.z); As[nb][akg0*4+3][am0] = to_tf32(ra0.w);
            As[nb][akg1*4+0][am1] = to_tf32(ra1.x); As[nb][akg1*4+1][am1] = to_tf32(ra1.y);
            As[nb][akg1*4+2][am1] = to_tf32(ra1.z); As[nb][akg1*4+3][am1] = to_tf32(ra1.w);
            if (!TRANSB) {
                float4 t2; t2.x = to_tf32(rb.x); t2.y = to_tf32(rb.y); t2.z = to_tf32(rb.z); t2.w = to_tf32(rb.w);
                *(float4*)&Bs[nb][bk][bng*4] = t2;
            } else {
                Bs[nb][btkg*4+0][btn] = to_tf32(rb.x); Bs[nb][btkg*4+1][btn] = to_tf32(rb.y);
                Bs[nb][btkg*4+2][btn] = to_tf32(rb.z); Bs[nb][btkg*4+3][btn] = to_tf32(rb.w);
            }
            __syncthreads();
        }
    }

    // epilogue
    #pragma unroll
    for (int mi = 0; mi < 2; mi++) {
        const int r = m0 + wm + mi*16 + (lane >> 2);
        #pragma unroll
        for (int ni = 0; ni < 4; ni++) {
            const int c = n0 + wn + ni*8 + 2*(lane & 3);
            float v00 = acc[mi][ni][0], v01 = acc[mi][ni][1];
            float v10 = acc[mi][ni][2], v11 = acc[mi][ni][3];
            if (EPI) {
                const float ea0 = ep_alpha[r], ea1 = ep_alpha[r+8];
                const float eb0 = ep_bias[c], eb1 = ep_bias[c+1];
                float2 ad0 = *(const float2*)(ep_add + (size_t)r*N + c);
                float2 ad1 = *(const float2*)(ep_add + (size_t)(r+8)*N + c);
                v00 += ea0*eb0 + ad0.x; v01 += ea0*eb1 + ad0.y;
                v10 += ea1*eb0 + ad1.x; v11 += ea1*eb1 + ad1.y;
            }
            float2 o0; o0.x = v00; o0.y = v01;
            float2 o1; o1.x = v10; o1.y = v11;
            *(float2*)(C + (size_t)r*N + c) = o0;
            *(float2*)(C + (size_t)(r+8)*N + c) = o1;
        }
    }
}

__global__ void __launch_bounds__(256)
k1_kernel(const float* __restrict__ Wu, const float* __restrict__ Wk,
          const float* __restrict__ Wv) {
    gemm_tc<DIMn, DIMn, false, false>(Wu, blockIdx.z ? Wv : Wk,
                                      blockIdx.z ? g_Wuv : g_Wuk,
                                      nullptr, nullptr, nullptr);
}
__global__ void __launch_bounds__(256)
k2b_kernel(const float* __restrict__ x) {
    gemm_tc<CVn, DIMn, true, false>(x, g_Wuk, g_P, nullptr, nullptr, nullptr);
}
__global__ void __launch_bounds__(256)
k6_kernel(const float* __restrict__ x, float* __restrict__ out) {
    gemm_tc<DIMn, CVn, false, true>(g_w, g_Wuv, out, g_alpha, g_buv, x);
}

// ---------------- bias: split-K partials + deterministic combine ----------------
__global__ void __launch_bounds__(256)
bias_part_kernel(const float* __restrict__ bu, const float* __restrict__ Wk,
                 const float* __restrict__ Wv) {
    int tid = threadIdx.x;
    const float* W = blockIdx.z ? Wv : Wk;
    int j = blockIdx.x * 256 + tid;
    int d0 = blockIdx.y * 128;
    __shared__ float sbu[128];
    if (tid < 128) sbu[tid] = bu[d0 + tid];
    __syncthreads();
    float acc = 0.f;
    #pragma unroll 8
    for (int dd = 0; dd < 128; dd++) acc += sbu[dd] * W[(size_t)(d0 + dd)*DIMn + j];
    g_bias_part[blockIdx.z][blockIdx.y][j] = acc;
}
__global__ void __launch_bounds__(256)
bias_combine_kernel() {
    int j = blockIdx.x * 256 + threadIdx.x;
    int z = blockIdx.y;
    float a = 0.f;
    #pragma unroll
    for (int p = 0; p < 8; p++) a += g_bias_part[z][p][j];
    (z ? g_buv : g_buk)[j] = a;
}

// ---------------- index build (warp-scan) + bq ----------------
__global__ void __launch_bounds__(256)
build_idx_kernel(const void* __restrict__ maskp, const float* __restrict__ x) {
    int bt = blockIdx.x, b = bt >> 8, t = bt & 255;
    int tid = threadIdx.x, lane = tid & 31, wid = tid >> 5;
    const bool u8 = (g_mask_u8 != 0);
    const unsigned char* m8 = (const unsigned char*)maskp;
    const int* m32 = (const int*)maskp;

    int vbase = tid << 2;
    int flags = 0, cnt = 0;
    #pragma unroll
    for (int u = 0; u < 4; u++) {
        int e = (b*Vn + vbase + u)*Tn + t;
        int mm = u8 ? (int)m8[e] : (m32[e] != 0);
        if (mm) { flags |= (1 << u); cnt++; }
    }
    int val = cnt;
    #pragma unroll
    for (int off = 1; off < 32; off <<= 1) {
        int v = __shfl_up_sync(0xffffffffu, val, off);
        if (lane >= off) val += v;
    }
    __shared__ int wtot[8];
    if (lane == 31) wtot[wid] = val;
    __syncthreads();
    int woff = 0, total = 0;
    #pragma unroll
    for (int w = 0; w < 8; w++) { int tw = wtot[w]; if (w < wid) woff += tw; total += tw; }
    int pos = woff + val - cnt;
    #pragma unroll
    for (int u = 0; u < 4; u++)
        if (flags & (1 << u)) { if (pos < Sn) g_idx[bt*Sn + pos] = vbase + u; pos++; }
    if (tid == 0)
        for (int p = total; p < Sn; p++) g_idx[bt*Sn + p] = Vn;

    // bq = buk . q
    float a = 0.f;
    #pragma unroll
    for (int u = 0; u < 4; u++)
        a += x[(size_t)bt*DIMn + vbase + u] * g_buk[vbase + u];
    #pragma unroll
    for (int off = 16; off; off >>= 1) a += __shfl_down_sync(0xffffffffu, a, off);
    __shared__ float wsm[8];
    if (lane == 0) wsm[wid] = a;
    __syncthreads();
    if (tid == 0) {
        float s = 0.f;
        #pragma unroll
        for (int w = 0; w < 8; w++) s += wsm[w];
        g_bq[bt] = s;
    }
}

// ---------------- logits ----------------
__global__ void __launch_bounds__(256)
logits_kernel(const float* __restrict__ vision) {
    int bt = blockIdx.x, b = bt >> 8, tid = threadIdx.x;
    __shared__ __align__(16) float p_sh[CVn];
    __shared__ int idx_sh[Sn];
    p_sh[tid] = g_P[bt*CVn + tid];
    if (tid < Sn) idx_sh[tid] = g_idx[bt*Sn + tid];
    __syncthreads();
    int s = tid >> 2, lane = tid & 3;
    int idx = idx_sh[s];
    float acc = 0.f;
    if (idx < Vn) {
        const float4* v4 = (const float4*)(vision + ((size_t)b*Vn + idx)*CVn);
        const float4* p4 = (const float4*)p_sh;
        #pragma unroll
        for (int c = lane; c < 64; c += 4) {
            float4 vv = v4[c], pp = p4[c];
            acc += vv.x*pp.x + vv.y*pp.y + vv.z*pp.z + vv.w*pp.w;
        }
    }
    acc += __shfl_down_sync(0xffffffffu, acc, 2, 4);
    acc += __shfl_down_sync(0xffffffffu, acc, 1, 4);
    if (lane == 0)
        g_logit[bt*Sn + s] = (acc + g_bq[bt]) * 0.03125f + (idx < Vn ? -100.0f : 0.0f);
}

// ---------------- batch-global softmax ----------------
__global__ void __launch_bounds__(1024)
softmax_kernel() {
    int b = blockIdx.x, tid = threadIdx.x;
    const int n = Tn * Sn;
    __shared__ float red[1024];
    float* L = g_logit + b * n;
    float* Sm = g_sm + b * n;

    float mx = -1e30f;
    for (int i = tid; i < n; i += 1024) mx = fmaxf(mx, L[i]);
    red[tid] = mx; __syncthreads();
    for (int off = 512; off > 0; off >>= 1) {
        if (tid < off) red[tid] = fmaxf(red[tid], red[tid + off]);
        __syncthreads();
    }
    mx = red[0]; __syncthreads();

    float sum = 0.f;
    for (int i = tid; i < n; i += 1024) {
        float e = __expf(L[i] - mx);
        Sm[i] = e; sum += e;
    }
    red[tid] = sum; __syncthreads();
    for (int off = 512; off > 0; off >>= 1) {
        if (tid < off) red[tid] += red[tid + off];
        __syncthreads();
    }
    float inv = 1.0f / red[0];
    for (int i = tid; i < n; i += 1024) Sm[i] *= inv;
}

// ---------------- w = sum_s sm * vg ; alpha = sum_s sm ----------------
__global__ void __launch_bounds__(64)
wsum_kernel(const float* __restrict__ vision) {
    int bt = blockIdx.x, b = bt >> 8, tid = threadIdx.x;
    __shared__ float sm_sh[Sn];
    __shared__ int idx_sh[Sn];
    sm_sh[tid] = g_sm[bt*Sn + tid];
    idx_sh[tid] = g_idx[bt*Sn + tid];
    __syncthreads();
    float4 acc = make_float4(0.f, 0.f, 0.f, 0.f);
    const float4* vb = (const float4*)(vision + (size_t)b*Vn*CVn);
    #pragma unroll 8
    for (int s = 0; s < Sn; s++) {
        int idx = idx_sh[s];
        if (idx < Vn) {
            float w = sm_sh[s];
            float4 v = vb[(size_t)idx*64 + tid];
            acc.x += w*v.x; acc.y += w*v.y; acc.z += w*v.z; acc.w += w*v.w;
        }
    }
    ((float4*)g_w)[(size_t)bt*64 + tid] = acc;

    float a = sm_sh[tid];
    #pragma unroll
    for (int off = 16; off; off >>= 1) a += __shfl_down_sync(0xffffffffu, a, off);
    __shared__ float w2[2];
    if ((tid & 31) == 0) w2[tid >> 5] = a;
    __syncthreads();
    if (tid == 0) g_alpha[bt] = w2[0] + w2[1];
}

// ---------------- launch ----------------
extern "C" void kernel_launch(void* const* d_in, const int* in_sizes, int n_in,
                              void* d_out, int out_size) {
    const float* x      = (const float*)d_in[0];
    const float* vision = (const float*)d_in[1];
    const void*  mask   = d_in[2];
    const float* Wu     = (const float*)d_in[3];
    const float* bu     = (const float*)d_in[4];
    const float* Wk     = (const float*)d_in[5];
    const float* Wv     = (const float*)d_in[6];
    float* out = (float*)d_out;

    detect_mask_kernel<<<1, 256>>>((const unsigned char*)mask);
    k1_kernel<<<dim3(DIMn/64, CVn/128, 2), 256>>>(Wu, Wk, Wv);     // Wuk, Wuv
    bias_part_kernel<<<dim3(DIMn/256, 8, 2), 256>>>(bu, Wk, Wv);
    bias_combine_kernel<<<dim3(DIMn/256, 2), 256>>>();             // buk, buv
    build_idx_kernel<<<BT, 256>>>(mask, x);                        // idx, bq
    k2b_kernel<<<dim3(CVn/64, BT/128), 256>>>(x);                  // P
    logits_kernel<<<BT, 256>>>(vision);                            // qk logits
    softmax_kernel<<<Bn, 1024>>>();                                // batch-global softmax
    wsum_kernel<<<BT, 64>>>(vision);                               // w, alpha
    k6_kernel<<<dim3(DIMn/64, BT/128), 256>>>(x, out);             // final GEMM + residual
}

// round 3
// speedup vs baseline: 2.8540x; 1.1010x over previous
#include <cuda_runtime.h>
#include <math.h>
#include <stdint.h>

#define Bn   4
#define Tn   256
#define Vn   1024
#define Sn   64
#define DIMn 1024
#define CVn  256
#define BT   (Bn*Tn)          // 1024

// ---------------- scratch ----------------
__device__ float g_Wuk[CVn*DIMn];
__device__ float g_Wuv[CVn*DIMn];
__device__ float g_bias_part[2][16][DIMn];
__device__ float g_buk[DIMn];
__device__ float g_buv[DIMn];
__device__ int   g_idx[BT*Sn];
__device__ float g_P[BT*CVn];
__device__ float g_wp[BT*CVn];     // unnormalized sum_s e_s * vg_s
__device__ float g_alpha[BT];      // unnormalized sum_s e_s

// ---------------- tf32 helpers ----------------
__device__ __forceinline__ float to_tf32(float x) {
    float r; asm("cvt.rna.tf32.f32 %0, %1;" : "=f"(r) : "f"(x)); return r;
}
__device__ __forceinline__ void mma_tf32(float c[4], const uint32_t a[4], const uint32_t b[2]) {
    asm volatile("mma.sync.aligned.m16n8k8.row.col.f32.tf32.tf32.f32 "
        "{%0,%1,%2,%3}, {%4,%5,%6,%7}, {%8,%9}, {%0,%1,%2,%3};"
        : "+f"(c[0]), "+f"(c[1]), "+f"(c[2]), "+f"(c[3])
        : "r"(a[0]), "r"(a[1]), "r"(a[2]), "r"(a[3]), "r"(b[0]), "r"(b[1]));
}

// ---------------- 64x64 tile tf32 GEMM body, 128 threads (4 warps of 32x32) ----------------
// C[M,N] = A[M,K](row) * B ; B row-major [K,N] (TRANSB=0) or [N,K] (TRANSB=1)
#define KTILE 16
#define SPAD  72

template<int N, int K, bool TRANSB, bool EPI>
__device__ __forceinline__ void gemm_body(int m0, int n0,
                                          const float* __restrict__ A,
                                          const float* __restrict__ Bm,
                                          float* __restrict__ C,
                                          float As[2][KTILE][SPAD],
                                          float Bs[2][KTILE][SPAD],
                                          const float* __restrict__ ep_alpha,
                                          const float* __restrict__ ep_bias,
                                          const float* __restrict__ ep_add,
                                          float ep_scale)
{
    const int tid  = threadIdx.x;
    const int lane = tid & 31, wid = tid >> 5;
    const int wm = (wid & 1) * 32;
    const int wn = (wid >> 1) * 32;

    // staging indices
    const int am0 = tid >> 2,            akg0 = tid & 3;          // A: 2 x 128 float4
    const int am1 = (tid + 128) >> 2,    akg1 = (tid + 128) & 3;
    const int bk0 = tid >> 4,            bc   = tid & 15;          // B no-trans rows
    const int btn0 = tid >> 2,           btkg = tid & 3;           // B trans rows

    float acc[2][4][4];
    #pragma unroll
    for (int i = 0; i < 2; i++)
        #pragma unroll
        for (int j = 0; j < 4; j++)
            #pragma unroll
            for (int q = 0; q < 4; q++) acc[i][j][q] = 0.f;

    float4 ra0, ra1, rb0, rb1;
    ra0 = *(const float4*)(A + (size_t)(m0 + am0)*K + akg0*4);
    ra1 = *(const float4*)(A + (size_t)(m0 + am1)*K + akg1*4);
    if (!TRANSB) {
        rb0 = *(const float4*)(Bm + (size_t)(bk0    )*N + n0 + bc*4);
        rb1 = *(const float4*)(Bm + (size_t)(bk0 + 8)*N + n0 + bc*4);
    } else {
        rb0 = *(const float4*)(Bm + (size_t)(n0 + btn0     )*K + btkg*4);
        rb1 = *(const float4*)(Bm + (size_t)(n0 + btn0 + 32)*K + btkg*4);
    }

    const int niter = K / KTILE;
    // store tile 0
    As[0][akg0*4+0][am0] = to_tf32(ra0.x); As[0][akg0*4+1][am0] = to_tf32(ra0.y);
    As[0][akg0*4+2][am0] = to_tf32(ra0.z); As[0][akg0*4+3][am0] = to_tf32(ra0.w);
    As[0][akg1*4+0][am1] = to_tf32(ra1.x); As[0][akg1*4+1][am1] = to_tf32(ra1.y);
    As[0][akg1*4+2][am1] = to_tf32(ra1.z); As[0][akg1*4+3][am1] = to_tf32(ra1.w);
    if (!TRANSB) {
        float4 t0, t1;
        t0.x = to_tf32(rb0.x); t0.y = to_tf32(rb0.y); t0.z = to_tf32(rb0.z); t0.w = to_tf32(rb0.w);
        t1.x = to_tf32(rb1.x); t1.y = to_tf32(rb1.y); t1.z = to_tf32(rb1.z); t1.w = to_tf32(rb1.w);
        *(float4*)&Bs[0][bk0  ][bc*4] = t0;
        *(float4*)&Bs[0][bk0+8][bc*4] = t1;
    } else {
        Bs[0][btkg*4+0][btn0] = to_tf32(rb0.x); Bs[0][btkg*4+1][btn0] = to_tf32(rb0.y);
        Bs[0][btkg*4+2][btn0] = to_tf32(rb0.z); Bs[0][btkg*4+3][btn0] = to_tf32(rb0.w);
        Bs[0][btkg*4+0][btn0+32] = to_tf32(rb1.x); Bs[0][btkg*4+1][btn0+32] = to_tf32(rb1.y);
        Bs[0][btkg*4+2][btn0+32] = to_tf32(rb1.z); Bs[0][btkg*4+3][btn0+32] = to_tf32(rb1.w);
    }
    __syncthreads();

    for (int it = 0; it < niter; it++) {
        const int buf = it & 1;
        const bool hasnext = (it + 1 < niter);
        if (hasnext) {
            const int kt = (it + 1) * KTILE;
            ra0 = *(const float4*)(A + (size_t)(m0 + am0)*K + kt + akg0*4);
            ra1 = *(const float4*)(A + (size_t)(m0 + am1)*K + kt + akg1*4);
            if (!TRANSB) {
                rb0 = *(const float4*)(Bm + (size_t)(kt + bk0    )*N + n0 + bc*4);
                rb1 = *(const float4*)(Bm + (size_t)(kt + bk0 + 8)*N + n0 + bc*4);
            } else {
                rb0 = *(const float4*)(Bm + (size_t)(n0 + btn0     )*K + kt + btkg*4);
                rb1 = *(const float4*)(Bm + (size_t)(n0 + btn0 + 32)*K + kt + btkg*4);
            }
        }
        #pragma unroll
        for (int ks = 0; ks < KTILE; ks += 8) {
            uint32_t af[2][4], bf[4][2];
            #pragma unroll
            for (int mi = 0; mi < 2; mi++) {
                const int row = wm + mi*16 + (lane >> 2);
                const int col = ks + (lane & 3);
                af[mi][0] = __float_as_uint(As[buf][col  ][row  ]);
                af[mi][1] = __float_as_uint(As[buf][col  ][row+8]);
                af[mi][2] = __float_as_uint(As[buf][col+4][row  ]);
                af[mi][3] = __float_as_uint(As[buf][col+4][row+8]);
            }
            #pragma unroll
            for (int ni = 0; ni < 4; ni++) {
                const int bcn = wn + ni*8 + (lane >> 2);
                bf[ni][0] = __float_as_uint(Bs[buf][ks   + (lane & 3)][bcn]);
                bf[ni][1] = __float_as_uint(Bs[buf][ks+4 + (lane & 3)][bcn]);
            }
            #pragma unroll
            for (int mi = 0; mi < 2; mi++)
                #pragma unroll
                for (int ni = 0; ni < 4; ni++)
                    mma_tf32(acc[mi][ni], af[mi], bf[ni]);
        }
        if (hasnext) {
            const int nb = buf ^ 1;
            As[nb][akg0*4+0][am0] = to_tf32(ra0.x); As[nb][akg0*4+1][am0] = to_tf32(ra0.y);
            As[nb][akg0*4+2][am0] = to_tf32(ra0.z); As[nb][akg0*4+3][am0] = to_tf32(ra0.w);
            As[nb][akg1*4+0][am1] = to_tf32(ra1.x); As[nb][akg1*4+1][am1] = to_tf32(ra1.y);
            As[nb][akg1*4+2][am1] = to_tf32(ra1.z); As[nb][akg1*4+3][am1] = to_tf32(ra1.w);
            if (!TRANSB) {
                float4 t0, t1;
                t0.x = to_tf32(rb0.x); t0.y = to_tf32(rb0.y); t0.z = to_tf32(rb0.z); t0.w = to_tf32(rb0.w);
                t1.x = to_tf32(rb1.x); t1.y = to_tf32(rb1.y); t1.z = to_tf32(rb1.z); t1.w = to_tf32(rb1.w);
                *(float4*)&Bs[nb][bk0  ][bc*4] = t0;
                *(float4*)&Bs[nb][bk0+8][bc*4] = t1;
            } else {
                Bs[nb][btkg*4+0][btn0] = to_tf32(rb0.x); Bs[nb][btkg*4+1][btn0] = to_tf32(rb0.y);
                Bs[nb][btkg*4+2][btn0] = to_tf32(rb0.z); Bs[nb][btkg*4+3][btn0] = to_tf32(rb0.w);
                Bs[nb][btkg*4+0][btn0+32] = to_tf32(rb1.x); Bs[nb][btkg*4+1][btn0+32] = to_tf32(rb1.y);
                Bs[nb][btkg*4+2][btn0+32] = to_tf32(rb1.z); Bs[nb][btkg*4+3][btn0+32] = to_tf32(rb1.w);
            }
            __syncthreads();
        }
    }

    #pragma unroll
    for (int mi = 0; mi < 2; mi++) {
        const int r = m0 + wm + mi*16 + (lane >> 2);
        #pragma unroll
        for (int ni = 0; ni < 4; ni++) {
            const int c = n0 + wn + ni*8 + 2*(lane & 3);
            float v00 = acc[mi][ni][0], v01 = acc[mi][ni][1];
            float v10 = acc[mi][ni][2], v11 = acc[mi][ni][3];
            if (EPI) {
                const float ea0 = ep_alpha[r], ea1 = ep_alpha[r+8];
                const float eb0 = ep_bias[c],  eb1 = ep_bias[c+1];
                float2 ad0 = *(const float2*)(ep_add + (size_t)r*N + c);
                float2 ad1 = *(const float2*)(ep_add + (size_t)(r+8)*N + c);
                v00 = (v00 + ea0*eb0)*ep_scale + ad0.x;
                v01 = (v01 + ea0*eb1)*ep_scale + ad0.y;
                v10 = (v10 + ea1*eb0)*ep_scale + ad1.x;
                v11 = (v11 + ea1*eb1)*ep_scale + ad1.y;
            }
            float2 o0; o0.x = v00; o0.y = v01;
            float2 o1; o1.x = v10; o1.y = v11;
            *(float2*)(C + (size_t)r*N + c) = o0;
            *(float2*)(C + (size_t)(r+8)*N + c) = o1;
        }
    }
}

// ---------------- prep: k1 GEMMs (128 blocks) + bias partials (32) + build_idx (1024) ----------------
__global__ void __launch_bounds__(128)
prep_kernel(const float* __restrict__ Wu, const float* __restrict__ Wk,
            const float* __restrict__ Wv, const float* __restrict__ bu,
            const void* __restrict__ maskp) {
    __shared__ __align__(16) float As[2][KTILE][SPAD];
    __shared__ __align__(16) float Bs[2][KTILE][SPAD];
    const int bid = blockIdx.x;
    const int tid = threadIdx.x;

    if (bid < 128) {
        // k1: Wuk / Wuv   M=256, N=1024, K=1024
        const int z = bid >> 6, t = bid & 63;
        const int m0 = (t >> 4) * 64, n0 = (t & 15) * 64;
        gemm_body<DIMn, DIMn, false, false>(m0, n0, Wu, z ? Wv : Wk,
                                            z ? g_Wuv : g_Wuk, As, Bs,
                                            nullptr, nullptr, nullptr, 0.f);
    } else if (bid < 160) {
        // bias split-K partials: 16 d-slices x 2 matrices
        const int r = bid - 128;
        const int z = r & 1, slice = r >> 1;
        const float* W = z ? Wv : Wk;
        const int d0 = slice * 64;
        __shared__ float sbu[64];
        if (tid < 64) sbu[tid] = bu[d0 + tid];
        __syncthreads();
        float acc[8];
        #pragma unroll
        for (int k = 0; k < 8; k++) acc[k] = 0.f;
        for (int dd = 0; dd < 64; dd++) {
            const float bv = sbu[dd];
            const float* row = W + (size_t)(d0 + dd)*DIMn + tid;
            #pragma unroll
            for (int k = 0; k < 8; k++) acc[k] += bv * row[128*k];
        }
        #pragma unroll
        for (int k = 0; k < 8; k++) g_bias_part[z][slice][tid + 128*k] = acc[k];
    } else {
        // build_idx: one block per (b,t)
        const int bt = bid - 160, b = bt >> 8, t = bt & 255;
        const int lane = tid & 31, wid = tid >> 5;
        const unsigned char* m8 = (const unsigned char*)maskp;
        const int* m32 = (const int*)maskp;

        // inline mask-dtype detection: bytes at pos%4==1 over first 4KB
        int dsum = 0;
        #pragma unroll
        for (int u = 0; u < 8; u++) dsum += (m8[(tid*8 + u)*4 + 1] != 0);
        const bool u8 = (__syncthreads_or(dsum) != 0);

        int flags = 0, cnt = 0;
        #pragma unroll
        for (int u = 0; u < 8; u++) {
            const int v = tid*8 + u;
            const int e = (b*Vn + v)*Tn + t;
            const int mm = u8 ? (int)m8[e] : (m32[e] != 0);
            if (mm) { flags |= (1 << u); cnt++; }
        }
        int val = cnt;
        #pragma unroll
        for (int off = 1; off < 32; off <<= 1) {
            int vv = __shfl_up_sync(0xffffffffu, val, off);
            if (lane >= off) val += vv;
        }
        __shared__ int wtot[4];
        if (lane == 31) wtot[wid] = val;
        __syncthreads();
        int woff = 0, total = 0;
        #pragma unroll
        for (int w = 0; w < 4; w++) { int tw = wtot[w]; if (w < wid) woff += tw; total += tw; }
        int pos = woff + val - cnt;
        #pragma unroll
        for (int u = 0; u < 8; u++)
            if (flags & (1 << u)) { if (pos < Sn) g_idx[bt*Sn + pos] = tid*8 + u; pos++; }
        if (tid == 0)
            for (int p = total; p < Sn; p++) g_idx[bt*Sn + p] = Vn;
    }
}

// ---------------- k2b: P GEMM (64 blocks) + bias combine (8 blocks) ----------------
__global__ void __launch_bounds__(128)
k2b_kernel(const float* __restrict__ x) {
    __shared__ __align__(16) float As[2][KTILE][SPAD];
    __shared__ __align__(16) float Bs[2][KTILE][SPAD];
    const int bid = blockIdx.x;
    if (bid < 64) {
        // P[bt,i] = sum_d x[bt,d]*Wuk[i,d]   M=1024, N=256(K-major B), K=1024
        const int m0 = (bid >> 2) * 64, n0 = (bid & 3) * 64;
        gemm_body<CVn, DIMn, true, false>(m0, n0, x, g_Wuk, g_P, As, Bs,
                                          nullptr, nullptr, nullptr, 0.f);
    } else {
        const int j = (bid - 64)*128 + threadIdx.x;
        float a0 = 0.f, a1 = 0.f;
        #pragma unroll
        for (int p = 0; p < 16; p++) { a0 += g_bias_part[0][p][j]; a1 += g_bias_part[1][p][j]; }
        g_buk[j] = a0; g_buv[j] = a1;
    }
}

// ---------------- attn: bq + logits + exp + unnormalized wsum + alpha ----------------
#define VPAD 272
__global__ void __launch_bounds__(256)
attn_kernel(const float* __restrict__ x, const float* __restrict__ vision) {
    __shared__ __align__(16) float vg[32][VPAD];
    __shared__ __align__(16) float P_s[CVn];
    __shared__ float e_s[32];
    __shared__ int   idx_s[Sn];
    __shared__ float red_s[8];
    __shared__ float bq_sh;

    const int bt = blockIdx.x, b = bt >> 8, tid = threadIdx.x;
    const int lane = tid & 31, wid = tid >> 5;

    // stage P and idx; compute bq = buk . x_row
    P_s[tid] = g_P[bt*CVn + tid];
    if (tid < Sn) idx_s[tid] = g_idx[bt*Sn + tid];
    {
        float4 xv = *(const float4*)(x + (size_t)bt*DIMn + tid*4);
        float4 bv = *(const float4*)(g_buk + tid*4);
        float a = xv.x*bv.x + xv.y*bv.y + xv.z*bv.z + xv.w*bv.w;
        #pragma unroll
        for (int off = 16; off; off >>= 1) a += __shfl_down_sync(0xffffffffu, a, off);
        if (lane == 0) red_s[wid] = a;
    }
    __syncthreads();
    if (tid == 0) {
        float s = 0.f;
        #pragma unroll
        for (int w = 0; w < 8; w++) s += red_s[w];
        bq_sh = s;
    }
    __syncthreads();
    const float bq = bq_sh;

    float acc_c = 0.f;       // w'[bt, tid]
    float aacc = 0.f;        // alpha partial (threads 0..31)

    #pragma unroll
    for (int chunk = 0; chunk < 2; chunk++) {
        const int c0 = chunk * 32;
        // gather 32 rows into smem (zeros for pad)
        #pragma unroll
        for (int i = 0; i < 8; i++) {
            const int L = tid + 256*i;           // 0..2047 float4 slots
            const int s = L >> 6, c4 = L & 63;
            const int idx = idx_s[c0 + s];
            float4 v = make_float4(0.f, 0.f, 0.f, 0.f);
            if (idx < Vn)
                v = *(const float4*)(vision + ((size_t)(b*Vn + idx))*CVn + c4*4);
            *(float4*)&vg[s][c4*4] = v;
        }
        __syncthreads();
        // dot + exp: 8 lanes per row
        {
            const int sg = tid >> 3, l8 = tid & 7;
            float a = 0.f;
            #pragma unroll
            for (int i = 0; i < 8; i++) {
                const int c4 = l8 + 8*i;
                float4 vv = *(const float4*)&vg[sg][c4*4];
                float4 pp = *(const float4*)&P_s[c4*4];
                a += vv.x*pp.x + vv.y*pp.y + vv.z*pp.z + vv.w*pp.w;
            }
            a += __shfl_down_sync(0xffffffffu, a, 4, 8);
            a += __shfl_down_sync(0xffffffffu, a, 2, 8);
            a += __shfl_down_sync(0xffffffffu, a, 1, 8);
            if (l8 == 0) {
                const int idx = idx_s[c0 + sg];
                float lp = (a + bq) * 0.03125f + (idx < Vn ? 0.f : 100.f);
                e_s[sg] = __expf(fminf(lp, 80.f));
            }
        }
        __syncthreads();
        // accumulate w' and alpha
        if (tid < 32) aacc += e_s[tid];
        #pragma unroll 8
        for (int s = 0; s < 32; s++)
            acc_c += e_s[s] * vg[s][tid];
        __syncthreads();
    }

    g_wp[bt*CVn + tid] = acc_c;
    if (tid < 32) {
        float a = aacc;
        #pragma unroll
        for (int off = 16; off; off >>= 1) a += __shfl_down_sync(0xffffffffu, a, off);
        if (tid == 0) g_alpha[bt] = a;
    }
}

// ---------------- k6: out = (w'@Wuv + alpha'*buv)/Z_b + x ----------------
__global__ void __launch_bounds__(128)
k6_kernel(const float* __restrict__ x, float* __restrict__ out) {
    __shared__ __align__(16) float As[2][KTILE][SPAD];
    __shared__ __align__(16) float Bs[2][KTILE][SPAD];
    __shared__ float zred[4];
    const int tid = threadIdx.x, lane = tid & 31, wid = tid >> 5;
    const int m0 = (blockIdx.x >> 4) * 64, n0 = (blockIdx.x & 15) * 64;
    const int b = m0 >> 8;
    // Z_b = sum of alpha' over this batch's 256 rows
    float a = g_alpha[b*256 + tid] + g_alpha[b*256 + 128 + tid];
    #pragma unroll
    for (int off = 16; off; off >>= 1) a += __shfl_down_sync(0xffffffffu, a, off);
    if (lane == 0) zred[wid] = a;
    __syncthreads();
    const float invZ = 1.0f / (zred[0] + zred[1] + zred[2] + zred[3]);
    __syncthreads();
    gemm_body<DIMn, CVn, false, true>(m0, n0, g_wp, g_Wuv, out, As, Bs,
                                      g_alpha, g_buv, x, invZ);
}

// ---------------- launch ----------------
extern "C" void kernel_launch(void* const* d_in, const int* in_sizes, int n_in,
                              void* d_out, int out_size) {
    const float* x      = (const float*)d_in[0];
    const float* vision = (const float*)d_in[1];
    const void*  mask   = d_in[2];
    const float* Wu     = (const float*)d_in[3];
    const float* bu     = (const float*)d_in[4];
    const float* Wk     = (const float*)d_in[5];
    const float* Wv     = (const float*)d_in[6];
    float* out = (float*)d_out;

    prep_kernel<<<128 + 32 + BT, 128>>>(Wu, Wk, Wv, bu, mask); // Wuk,Wuv,bias parts,idx
    k2b_kernel<<<64 + 8, 128>>>(x);                            // P + buk/buv combine
    attn_kernel<<<BT, 256>>>(x, vision);                       // e, w', alpha'
    k6_kernel<<<256, 128>>>(x, out);                           // final GEMM + softmax norm + residual
}

// round 5
// speedup vs baseline: 5.4041x; 1.8935x over previous
#include <cuda_runtime.h>
#include <cuda_bf16.h>
#include <math.h>
#include <stdint.h>

#define Bn   4
#define Tn   256
#define Vn   1024
#define Sn   64
#define DIMn 1024
#define CVn  256
#define BT   (Bn*Tn)          // 1024
#define SW   72               // smem word stride (conflict-free: (8*k2+m)%32)

// ---------------- scratch ----------------
__device__ float g_pp[2][4][CVn*DIMn];     // k1 split-K partials (8 MB)
__device__ float g_Wuk[CVn*DIMn];
__device__ float g_Wuv[CVn*DIMn];
__device__ float g_bias_part[2][16][DIMn];
__device__ float g_buk[DIMn];
__device__ float g_buv[DIMn];
__device__ int   g_idx[BT*Sn];
__device__ float g_Ppart[4][BT*CVn];       // k2b split-K partials (4 MB)
__device__ float g_wp[BT*CVn];             // unnormalized sum_s e_s * vg_s
__device__ float g_alpha[BT];              // unnormalized sum_s e_s
__device__ float g_opart[2][BT*DIMn];      // k6 split-K partials (8 MB)
__device__ float g_invZ[Bn];

// ---------------- bf16 helpers ----------------
__device__ __forceinline__ uint32_t packbf(float x, float y) {
    __nv_bfloat162 h = __floats2bfloat162_rn(x, y);
    return *reinterpret_cast<uint32_t*>(&h);
}
__device__ __forceinline__ void mma_bf16(float c[4], const uint32_t a[4], const uint32_t b[2]) {
    asm volatile("mma.sync.aligned.m16n8k16.row.col.f32.bf16.bf16.f32 "
        "{%0,%1,%2,%3}, {%4,%5,%6,%7}, {%8,%9}, {%0,%1,%2,%3};"
        : "+f"(c[0]), "+f"(c[1]), "+f"(c[2]), "+f"(c[3])
        : "r"(a[0]), "r"(a[1]), "r"(a[2]), "r"(a[3]), "r"(b[0]), "r"(b[1]));
}

// ---------------- bf16 64x64-tile GEMM body, 128 threads (2x2 warps of 32x32) ----------------
// C[.., n0..] (row stride Nn) += A[m0.., k0..k0+ksub) (row stride Ks) * B
// B row-major [K,Nn] (TRANSB=0) or [N,Ks] (TRANSB=1).
template<int Nn, int Ks, bool TRANSB>
__device__ __forceinline__ void gemm_bf16(
    const int m0, const int n0, const int k0, const int ksub,
    const float* __restrict__ A, const float* __restrict__ Bm,
    float* __restrict__ C,
    uint32_t Ap[2][8][SW], uint32_t Bp[2][8][SW])
{
    const int tid = threadIdx.x, lane = tid & 31, wid = tid >> 5;
    const int wm = (wid & 1) * 32, wn = (wid >> 1) * 32;
    const int am0 = tid >> 2,         ag0 = tid & 3;
    const int am1 = (tid + 128) >> 2, ag1 = (tid + 128) & 3;
    const int bk2 = tid >> 4,         bng = tid & 15;

    float acc[2][4][4];
    #pragma unroll
    for (int i = 0; i < 2; i++)
        #pragma unroll
        for (int j = 0; j < 4; j++)
            #pragma unroll
            for (int q = 0; q < 4; q++) acc[i][j][q] = 0.f;

    float4 ra0, ra1, rb0, rb1;

    auto loadg = [&](int kt) {
        ra0 = *(const float4*)(A + (size_t)(m0 + am0)*Ks + k0 + kt + ag0*4);
        ra1 = *(const float4*)(A + (size_t)(m0 + am1)*Ks + k0 + kt + ag1*4);
        if (!TRANSB) {
            rb0 = *(const float4*)(Bm + (size_t)(k0 + kt + 2*bk2    )*Nn + n0 + bng*4);
            rb1 = *(const float4*)(Bm + (size_t)(k0 + kt + 2*bk2 + 1)*Nn + n0 + bng*4);
        } else {
            rb0 = *(const float4*)(Bm + (size_t)(n0 + am0)*Ks + k0 + kt + ag0*4);
            rb1 = *(const float4*)(Bm + (size_t)(n0 + am1)*Ks + k0 + kt + ag1*4);
        }
    };
    auto stores = [&](int buf) {
        Ap[buf][ag0*2    ][am0] = packbf(ra0.x, ra0.y);
        Ap[buf][ag0*2 + 1][am0] = packbf(ra0.z, ra0.w);
        Ap[buf][ag1*2    ][am1] = packbf(ra1.x, ra1.y);
        Ap[buf][ag1*2 + 1][am1] = packbf(ra1.z, ra1.w);
        if (!TRANSB) {
            uint4 q;
            q.x = packbf(rb0.x, rb1.x); q.y = packbf(rb0.y, rb1.y);
            q.z = packbf(rb0.z, rb1.z); q.w = packbf(rb0.w, rb1.w);
            *(uint4*)&Bp[buf][bk2][bng*4] = q;
        } else {
            Bp[buf][ag0*2    ][am0] = packbf(rb0.x, rb0.y);
            Bp[buf][ag0*2 + 1][am0] = packbf(rb0.z, rb0.w);
            Bp[buf][ag1*2    ][am1] = packbf(rb1.x, rb1.y);
            Bp[buf][ag1*2 + 1][am1] = packbf(rb1.z, rb1.w);
        }
    };

    loadg(0); stores(0); __syncthreads();
    const int niter = ksub >> 4;
    for (int it = 0; it < niter; it++) {
        const int buf = it & 1;
        const bool nxt = (it + 1 < niter);
        if (nxt) loadg((it + 1) << 4);

        uint32_t af[2][4], bfr[4][2];
        #pragma unroll
        for (int mi = 0; mi < 2; mi++) {
            const int row = wm + mi*16 + (lane >> 2);
            af[mi][0] = Ap[buf][    (lane & 3)][row];
            af[mi][1] = Ap[buf][    (lane & 3)][row + 8];
            af[mi][2] = Ap[buf][4 + (lane & 3)][row];
            af[mi][3] = Ap[buf][4 + (lane & 3)][row + 8];
        }
        #pragma unroll
        for (int ni = 0; ni < 4; ni++) {
            const int col = wn + ni*8 + (lane >> 2);
            bfr[ni][0] = Bp[buf][    (lane & 3)][col];
            bfr[ni][1] = Bp[buf][4 + (lane & 3)][col];
        }
        #pragma unroll
        for (int mi = 0; mi < 2; mi++)
            #pragma unroll
            for (int ni = 0; ni < 4; ni++)
                mma_bf16(acc[mi][ni], af[mi], bfr[ni]);

        if (nxt) { stores(buf ^ 1); __syncthreads(); }
    }

    #pragma unroll
    for (int mi = 0; mi < 2; mi++) {
        const int r = m0 + wm + mi*16 + (lane >> 2);
        #pragma unroll
        for (int ni = 0; ni < 4; ni++) {
            const int c = n0 + wn + ni*8 + 2*(lane & 3);
            float2 o0, o1;
            o0.x = acc[mi][ni][0]; o0.y = acc[mi][ni][1];
            o1.x = acc[mi][ni][2]; o1.y = acc[mi][ni][3];
            *(float2*)(C + (size_t)r*Nn + c) = o0;
            *(float2*)(C + (size_t)(r + 8)*Nn + c) = o1;
        }
    }
}

// ---------------- prep: k1 partials (512) + bias partials (32) + build_idx (1024) ----------------
__global__ void __launch_bounds__(128)
prep_kernel(const float* __restrict__ Wu, const float* __restrict__ Wk,
            const float* __restrict__ Wv, const float* __restrict__ bu,
            const void* __restrict__ maskp) {
    __shared__ __align__(16) uint32_t Ap[2][8][SW];
    __shared__ __align__(16) uint32_t Bp[2][8][SW];
    const int bid = blockIdx.x;
    const int tid = threadIdx.x;

    if (bid < 512) {
        // Wuk/Wuv: M=256, N=1024, K=1024 split 4x256
        const int z = bid >> 8, r = bid & 255;
        const int ks = r >> 6, t = r & 63;
        const int m0 = (t >> 4) * 64, n0 = (t & 15) * 64;
        gemm_bf16<DIMn, DIMn, false>(m0, n0, ks*256, 256, Wu, z ? Wv : Wk,
                                     g_pp[z][ks], Ap, Bp);
    } else if (bid < 544) {
        const int r = bid - 512;
        const int z = r & 1, slice = r >> 1;
        const float* W = z ? Wv : Wk;
        const int d0 = slice * 64;
        __shared__ float sbu[64];
        if (tid < 64) sbu[tid] = bu[d0 + tid];
        __syncthreads();
        float acc[8];
        #pragma unroll
        for (int k = 0; k < 8; k++) acc[k] = 0.f;
        for (int dd = 0; dd < 64; dd++) {
            const float bv = sbu[dd];
            const float* row = W + (size_t)(d0 + dd)*DIMn + tid;
            #pragma unroll
            for (int k = 0; k < 8; k++) acc[k] += bv * row[128*k];
        }
        #pragma unroll
        for (int k = 0; k < 8; k++) g_bias_part[z][slice][tid + 128*k] = acc[k];
    } else {
        // build_idx: one block per (b,t)
        const int bt = bid - 544, b = bt >> 8, t = bt & 255;
        const int lane = tid & 31, wid = tid >> 5;
        const unsigned char* m8 = (const unsigned char*)maskp;
        const int* m32 = (const int*)maskp;

        int dsum = 0;
        #pragma unroll
        for (int u = 0; u < 8; u++) dsum += (m8[(tid*8 + u)*4 + 1] != 0);
        const bool u8 = (__syncthreads_or(dsum) != 0);

        int flags = 0, cnt = 0;
        #pragma unroll
        for (int u = 0; u < 8; u++) {
            const int v = tid*8 + u;
            const int e = (b*Vn + v)*Tn + t;
            const int mm = u8 ? (int)m8[e] : (m32[e] != 0);
            if (mm) { flags |= (1 << u); cnt++; }
        }
        int val = cnt;
        #pragma unroll
        for (int off = 1; off < 32; off <<= 1) {
            int vv = __shfl_up_sync(0xffffffffu, val, off);
            if (lane >= off) val += vv;
        }
        __shared__ int wtot[4];
        if (lane == 31) wtot[wid] = val;
        __syncthreads();
        int woff = 0, total = 0;
        #pragma unroll
        for (int w = 0; w < 4; w++) { int tw = wtot[w]; if (w < wid) woff += tw; total += tw; }
        int pos = woff + val - cnt;
        #pragma unroll
        for (int u = 0; u < 8; u++)
            if (flags & (1 << u)) { if (pos < Sn) g_idx[bt*Sn + pos] = tid*8 + u; pos++; }
        if (tid == 0)
            for (int p = total; p < Sn; p++) g_idx[bt*Sn + p] = Vn;
    }
}

// ---------------- combine: Wuk/Wuv (512 blocks) + buk/buv (2 blocks) ----------------
__global__ void __launch_bounds__(128)
combine_kernel() {
    const int bid = blockIdx.x, tid = threadIdx.x;
    if (bid < 512) {
        #pragma unroll
        for (int h = 0; h < 2; h++) {
            const int F = bid*256 + h*128 + tid;          // float4 index over 2x64K
            const int z = F >> 16, off4 = F & 65535;
            float4 s = make_float4(0.f, 0.f, 0.f, 0.f);
            #pragma unroll
            for (int p = 0; p < 4; p++) {
                float4 v = ((const float4*)g_pp[z][p])[off4];
                s.x += v.x; s.y += v.y; s.z += v.z; s.w += v.w;
            }
            ((float4*)(z ? g_Wuv : g_Wuk))[off4] = s;
        }
    } else {
        const int z = bid - 512;
        #pragma unroll
        for (int h = 0; h < 8; h++) {
            const int j = h*128 + tid;
            float a = 0.f;
            #pragma unroll
            for (int p = 0; p < 16; p++) a += g_bias_part[z][p][j];
            (z ? g_buv : g_buk)[j] = a;
        }
    }
}

// ---------------- k2b: P partials, split-K x4 (256 blocks) ----------------
__global__ void __launch_bounds__(128)
k2b_kernel(const float* __restrict__ x) {
    __shared__ __align__(16) uint32_t Ap[2][8][SW];
    __shared__ __align__(16) uint32_t Bp[2][8][SW];
    const int bid = blockIdx.x;
    const int ks = bid >> 6, r = bid & 63;
    const int m0 = (r >> 2) * 64, n0 = (r & 3) * 64;
    gemm_bf16<CVn, DIMn, true>(m0, n0, ks*256, 256, x, g_Wuk, g_Ppart[ks], Ap, Bp);
}

// ---------------- attn: P combine + bq + logits + exp + unnormalized wsum ----------------
#define VPAD 272
__global__ void __launch_bounds__(256)
attn_kernel(const float* __restrict__ x, const float* __restrict__ vision) {
    __shared__ __align__(16) float vg[32][VPAD];
    __shared__ __align__(16) float P_s[CVn];
    __shared__ float e_s[32];
    __shared__ int   idx_s[Sn];
    __shared__ float red_s[8];
    __shared__ float bq_sh;

    const int bt = blockIdx.x, b = bt >> 8, tid = threadIdx.x;
    const int lane = tid & 31, wid = tid >> 5;

    P_s[tid] = g_Ppart[0][bt*CVn + tid] + g_Ppart[1][bt*CVn + tid]
             + g_Ppart[2][bt*CVn + tid] + g_Ppart[3][bt*CVn + tid];
    if (tid < Sn) idx_s[tid] = g_idx[bt*Sn + tid];
    {
        float4 xv = *(const float4*)(x + (size_t)bt*DIMn + tid*4);
        float4 bv = *(const float4*)(g_buk + tid*4);
        float a = xv.x*bv.x + xv.y*bv.y + xv.z*bv.z + xv.w*bv.w;
        #pragma unroll
        for (int off = 16; off; off >>= 1) a += __shfl_down_sync(0xffffffffu, a, off);
        if (lane == 0) red_s[wid] = a;
    }
    __syncthreads();
    if (tid == 0) {
        float s = 0.f;
        #pragma unroll
        for (int w = 0; w < 8; w++) s += red_s[w];
        bq_sh = s;
    }
    __syncthreads();
    const float bq = bq_sh;

    float acc_c = 0.f;
    float aacc = 0.f;

    #pragma unroll
    for (int chunk = 0; chunk < 2; chunk++) {
        const int c0 = chunk * 32;
        #pragma unroll
        for (int i = 0; i < 8; i++) {
            const int L = tid + 256*i;
            const int s = L >> 6, c4 = L & 63;
            const int idx = idx_s[c0 + s];
            float4 v = make_float4(0.f, 0.f, 0.f, 0.f);
            if (idx < Vn)
                v = *(const float4*)(vision + ((size_t)(b*Vn + idx))*CVn + c4*4);
            *(float4*)&vg[s][c4*4] = v;
        }
        __syncthreads();
        {
            const int sg = tid >> 3, l8 = tid & 7;
            float a = 0.f;
            #pragma unroll
            for (int i = 0; i < 8; i++) {
                const int c4 = l8 + 8*i;
                float4 vv = *(const float4*)&vg[sg][c4*4];
                float4 pp = *(const float4*)&P_s[c4*4];
                a += vv.x*pp.x + vv.y*pp.y + vv.z*pp.z + vv.w*pp.w;
            }
            a += __shfl_down_sync(0xffffffffu, a, 4, 8);
            a += __shfl_down_sync(0xffffffffu, a, 2, 8);
            a += __shfl_down_sync(0xffffffffu, a, 1, 8);
            if (l8 == 0) {
                const int idx = idx_s[c0 + sg];
                float lp = (a + bq) * 0.03125f + (idx < Vn ? 0.f : 100.f);
                e_s[sg] = __expf(fminf(lp, 80.f));
            }
        }
        __syncthreads();
        if (tid < 32) aacc += e_s[tid];
        #pragma unroll 8
        for (int s = 0; s < 32; s++)
            acc_c += e_s[s] * vg[s][tid];
        __syncthreads();
    }

    g_wp[bt*CVn + tid] = acc_c;
    if (tid < 32) {
        float a = aacc;
        #pragma unroll
        for (int off = 16; off; off >>= 1) a += __shfl_down_sync(0xffffffffu, a, off);
        if (tid == 0) g_alpha[bt] = a;
    }
}

// ---------------- k6part: out-GEMM partials split-K x2 (512) + invZ (4) ----------------
__global__ void __launch_bounds__(128)
k6part_kernel() {
    __shared__ __align__(16) uint32_t Ap[2][8][SW];
    __shared__ __align__(16) uint32_t Bp[2][8][SW];
    const int bid = blockIdx.x, tid = threadIdx.x;
    if (bid < 512) {
        const int ks = bid >> 8, r = bid & 255;
        const int m0 = (r >> 4) * 64, n0 = (r & 15) * 64;
        gemm_bf16<DIMn, CVn, false>(m0, n0, ks*128, 128, g_wp, g_Wuv,
                                    g_opart[ks], Ap, Bp);
    } else {
        const int b = bid - 512;
        const int lane = tid & 31, wid = tid >> 5;
        __shared__ float zr[4];
        float a = g_alpha[b*256 + tid] + g_alpha[b*256 + 128 + tid];
        #pragma unroll
        for (int off = 16; off; off >>= 1) a += __shfl_down_sync(0xffffffffu, a, off);
        if (lane == 0) zr[wid] = a;
        __syncthreads();
        if (tid == 0) g_invZ[b] = 1.0f / (zr[0] + zr[1] + zr[2] + zr[3]);
    }
}

// ---------------- finish: out = (p0+p1 + alpha*buv)*invZ + x ----------------
__global__ void __launch_bounds__(256)
finish_kernel(const float* __restrict__ x, float* __restrict__ out) {
    const int r = blockIdx.x, b = r >> 8, tid = threadIdx.x;
    const float al = g_alpha[r];
    const float iz = g_invZ[b];
    float4 p0 = ((const float4*)g_opart[0])[r*256 + tid];
    float4 p1 = ((const float4*)g_opart[1])[r*256 + tid];
    float4 bv = ((const float4*)g_buv)[tid];
    float4 xv = ((const float4*)x)[r*256 + tid];
    float4 o;
    o.x = (p0.x + p1.x + al*bv.x)*iz + xv.x;
    o.y = (p0.y + p1.y + al*bv.y)*iz + xv.y;
    o.z = (p0.z + p1.z + al*bv.z)*iz + xv.z;
    o.w = (p0.w + p1.w + al*bv.w)*iz + xv.w;
    ((float4*)out)[r*256 + tid] = o;
}

// ---------------- launch ----------------
extern "C" void kernel_launch(void* const* d_in, const int* in_sizes, int n_in,
                              void* d_out, int out_size) {
    const float* x      = (const float*)d_in[0];
    const float* vision = (const float*)d_in[1];
    const void*  mask   = d_in[2];
    const float* Wu     = (const float*)d_in[3];
    const float* bu     = (const float*)d_in[4];
    const float* Wk     = (const float*)d_in[5];
    const float* Wv     = (const float*)d_in[6];
    float* out = (float*)d_out;

    prep_kernel<<<512 + 32 + BT, 128>>>(Wu, Wk, Wv, bu, mask);
    combine_kernel<<<514, 128>>>();
    k2b_kernel<<<256, 128>>>(x);
    attn_kernel<<<BT, 256>>>(x, vision);
    k6part_kernel<<<516, 128>>>();
    finish_kernel<<<BT, 256>>>(x, out);
}